// round 14
// baseline (speedup 1.0000x reference)
#include <cuda_runtime.h>
#include <math.h>

#define BB   128
#define NN   512
#define FIN  5
#define HH   64
#define KNN  16
#define COUT 10
#define NODES (BB*NN)
#define HTS  520   // hT row stride in floats

typedef unsigned long long ull;

// ---------------- scratch (device globals) ----------------
__device__ float g_h0[NODES*HH];
__device__ float g_h1[NODES*HH];
__device__ float g_A [NODES*HH];
__device__ float g_U [NODES*HH];
__device__ int   g_knn[NODES*KNN];

// fast branchless ELU
__device__ __forceinline__ float elu1(float x) {
    float e = __expf(x) - 1.f;
    return x > 0.f ? x : e;
}

// ---- packed f32x2 helpers (Blackwell FFMA2 via PTX) ----
__device__ __forceinline__ ull pack2(float x, float y) {
    ull r; asm("mov.b64 %0, {%1,%2};" : "=l"(r) : "f"(x), "f"(y)); return r;
}
__device__ __forceinline__ float2 unpack2(ull v) {
    float2 f; asm("mov.b64 {%0,%1}, %2;" : "=f"(f.x), "=f"(f.y) : "l"(v)); return f;
}
__device__ __forceinline__ ull ffma2(ull a, ull b, ull c) {
    ull d; asm("fma.rn.f32x2 %0, %1, %2, %3;" : "=l"(d) : "l"(a), "l"(b), "l"(c)); return d;
}

__device__ __forceinline__ unsigned fflip(float f) {
    unsigned u = __float_as_uint(f);
    return ((int)u < 0) ? ~u : (u | 0x80000000u);
}

// Batcher odd-even mergesort, n=8, in-register, fully unrolled
__device__ __forceinline__ void sort8(ull key[8]) {
#pragma unroll
    for (int p = 1; p < 8; p <<= 1) {
#pragma unroll
        for (int k = p; k >= 1; k >>= 1) {
#pragma unroll
            for (int j = k % p; j + k < 8; j += 2*k) {
#pragma unroll
                for (int ii = 0; ii < k; ii++) {
                    int a = ii + j, c = ii + j + k;
                    if (c < 8 && (a / (2*p) == c / (2*p))) {
                        ull lo = key[a] < key[c] ? key[a] : key[c];
                        ull hi = key[a] < key[c] ? key[c] : key[a];
                        key[a] = lo; key[c] = hi;
                    }
                }
            }
        }
    }
}

// ---------------- fused 3-layer input MLP: x[5] -> 64 -> 64 -> 64, all ELU ----------------
__global__ __launch_bounds__(256) void k_lin_in(const float* __restrict__ in,
                                                const float* __restrict__ W0, const float* __restrict__ b0,
                                                const float* __restrict__ W1, const float* __restrict__ b1,
                                                const float* __restrict__ W2, const float* __restrict__ b2,
                                                float* __restrict__ out)
{
    __shared__ __align__(16) float sW0[FIN*HH];
    __shared__ __align__(16) float sW1[HH*HH];
    __shared__ __align__(16) float sW2[HH*HH];
    __shared__ float sb0[HH], sb1[HH], sb2[HH];
    int tid = threadIdx.x;
    for (int i = tid; i < FIN*HH; i += 256) sW0[i] = W0[i];
    for (int i = tid; i < HH*HH; i += 256) { sW1[i] = W1[i]; sW2[i] = W2[i]; }
    if (tid < HH) { sb0[tid] = b0[tid]; sb1[tid] = b1[tid]; sb2[tid] = b2[tid]; }
    __syncthreads();

    int node = blockIdx.x * 256 + tid;
    float xv[FIN];
#pragma unroll
    for (int d = 0; d < FIN; d++) xv[d] = in[node*FIN + d];

    float h[HH];
#pragma unroll
    for (int o = 0; o < HH; o++) {
        float a = sb0[o];
#pragma unroll
        for (int d = 0; d < FIN; d++) a += xv[d] * sW0[d*HH + o];
        h[o] = elu1(a);
    }

    float g[HH];
#pragma unroll 2
    for (int op = 0; op < 32; op++) {
        ull acc = 0ull;
#pragma unroll
        for (int d = 0; d < HH; d++)
            acc = ffma2(pack2(h[d], h[d]), ((const ull*)(sW1 + d*HH))[op], acc);
        float2 p = unpack2(acc);
        g[2*op]   = elu1(p.x + sb1[2*op]);
        g[2*op+1] = elu1(p.y + sb1[2*op+1]);
    }

#pragma unroll 2
    for (int op = 0; op < 32; op++) {
        ull acc = 0ull;
#pragma unroll
        for (int d = 0; d < HH; d++)
            acc = ffma2(pack2(g[d], g[d]), ((const ull*)(sW2 + d*HH))[op], acc);
        float2 p = unpack2(acc);
        float2 o2 = make_float2(elu1(p.x + sb2[2*op]), elu1(p.y + sb2[2*op+1]));
        *(float2*)&out[node*HH + 2*op] = o2;
    }
}

// ---------------- fused A/U pre-GEMMs + kNN, column-split warp pairs ----------------
// 512 threads, 16 warps. Warp pair (2w, 2w+1) handles 8 rows; each warp does 256 cols.
// smem: hT 130KB + sq 2KB + sbp 256B + union{ weights 32KB | wloc[16][2][8][32] 64KB + merge 16KB }
__global__ __launch_bounds__(512) void k_knn3(const float* __restrict__ h,
                                              const float* __restrict__ W0,
                                              const float* __restrict__ b0,
                                              int* __restrict__ kn,
                                              float* __restrict__ A,
                                              float* __restrict__ U)
{
    extern __shared__ __align__(16) char smraw[];
    float* hT  = (float*)smraw;                // [64][HTS]
    float* sq  = hT + HH*HTS;                  // [512]
    float* sbp = sq + NN;                      // [64]
    float* uni = sbp + HH;                     // union region (16-B aligned)
    float* sWb = uni;                          // [4096] (phase A)
    float* sWd = uni + HH*HH;                  // [4096] (phase A)
    ull*   wlocBase = (ull*)uni;               // [16 warps][2 rows][8][32] (phase B)
    ull*   mergeBuf = (ull*)uni + 16*2*8*32;   // [64 rows][32]            (phase B)

    int b = blockIdx.x, tid = threadIdx.x;
    int w = tid >> 5, lane = tid & 31;
    const float* hb = h + (size_t)b * NN * HH;

    // stage EdgeConv layer-0 weights (phase A) + bias
    for (int i = tid; i < HH*HH; i += 512) {
        float wa = W0[i];
        float wb = W0[HH*HH + i];
        sWb[i] = wb;
        sWd[i] = wa - wb;
    }
    if (tid < HH) sbp[tid] = b0[tid];

    // load + transpose features, fold in squared norms
    {
        const float4* src = (const float4*)(hb + (size_t)tid * HH);
        float s = 0.f;
#pragma unroll
        for (int q = 0; q < 16; q++) {
            float4 v = src[q];
            int d = q * 4;
            hT[(d+0)*HTS + tid] = v.x;
            hT[(d+1)*HTS + tid] = v.y;
            hT[(d+2)*HTS + tid] = v.z;
            hT[(d+3)*HTS + tid] = v.w;
            s += v.x*v.x + v.y*v.y + v.z*v.z + v.w*v.w;
        }
        sq[tid] = s;
    }
    __syncthreads();

    // ---------- phase A: A/U pre-GEMMs (weights live in union) ----------
    {
        int node = b*NN + tid;
        float hv[HH];
#pragma unroll
        for (int d = 0; d < HH; d++) hv[d] = hT[d*HTS + tid];

#pragma unroll 2
        for (int op = 0; op < 32; op++) {
            ull au = 0ull, ad = 0ull;
#pragma unroll
            for (int d = 0; d < HH; d++) {
                ull hp = pack2(hv[d], hv[d]);
                au = ffma2(hp, ((const ull*)(sWb + d*HH))[op], au);
                ad = ffma2(hp, ((const ull*)(sWd + d*HH))[op], ad);
            }
            float2 pu = unpack2(au);
            *(float2*)&U[(size_t)node*HH + 2*op] = pu;
            float2 pa = unpack2(ad);
            pa.x += sbp[2*op]; pa.y += sbp[2*op+1];
            *(float2*)&A[(size_t)node*HH + 2*op] = pa;
        }
    }
    __syncthreads();   // weight reads done; union becomes wloc/merge

    // ---------- phase B: kNN, 8 passes; warp pair = 8 rows, warp = 256 cols ----------
    int pairw = w >> 1;        // 0..7: row-group within pass
    int halfc = w & 1;         // column half: cols [halfc*256, +256)
    ull* wloc = wlocBase + w * (2*8*32);

#pragma unroll 1
    for (int pp = 0; pp < 8; pp++) {
        int i0 = pp*64 + pairw*8;      // 8 consecutive rows

        ull acc[8][4];
#pragma unroll
        for (int r = 0; r < 8; r++)
#pragma unroll
            for (int t = 0; t < 4; t++) acc[r][t] = 0ull;

#pragma unroll 2
        for (int d = 0; d < HH; d++) {
            const float* rowp = hT + d*HTS;
            float4 xa = *(const float4*)(rowp + i0);        // broadcast rows i0..i0+3
            float4 xb = *(const float4*)(rowp + i0 + 4);    // rows i0+4..i0+7
            const ull* bp = (const ull*)rowp + halfc*128;   // this warp's 256-col half
            ull bv0 = bp[lane], bv1 = bp[lane+32], bv2 = bp[lane+64], bv3 = bp[lane+96];
            ull xp;
            xp = pack2(xa.x, xa.x);
            acc[0][0]=ffma2(xp,bv0,acc[0][0]); acc[0][1]=ffma2(xp,bv1,acc[0][1]);
            acc[0][2]=ffma2(xp,bv2,acc[0][2]); acc[0][3]=ffma2(xp,bv3,acc[0][3]);
            xp = pack2(xa.y, xa.y);
            acc[1][0]=ffma2(xp,bv0,acc[1][0]); acc[1][1]=ffma2(xp,bv1,acc[1][1]);
            acc[1][2]=ffma2(xp,bv2,acc[1][2]); acc[1][3]=ffma2(xp,bv3,acc[1][3]);
            xp = pack2(xa.z, xa.z);
            acc[2][0]=ffma2(xp,bv0,acc[2][0]); acc[2][1]=ffma2(xp,bv1,acc[2][1]);
            acc[2][2]=ffma2(xp,bv2,acc[2][2]); acc[2][3]=ffma2(xp,bv3,acc[2][3]);
            xp = pack2(xa.w, xa.w);
            acc[3][0]=ffma2(xp,bv0,acc[3][0]); acc[3][1]=ffma2(xp,bv1,acc[3][1]);
            acc[3][2]=ffma2(xp,bv2,acc[3][2]); acc[3][3]=ffma2(xp,bv3,acc[3][3]);
            xp = pack2(xb.x, xb.x);
            acc[4][0]=ffma2(xp,bv0,acc[4][0]); acc[4][1]=ffma2(xp,bv1,acc[4][1]);
            acc[4][2]=ffma2(xp,bv2,acc[4][2]); acc[4][3]=ffma2(xp,bv3,acc[4][3]);
            xp = pack2(xb.y, xb.y);
            acc[5][0]=ffma2(xp,bv0,acc[5][0]); acc[5][1]=ffma2(xp,bv1,acc[5][1]);
            acc[5][2]=ffma2(xp,bv2,acc[5][2]); acc[5][3]=ffma2(xp,bv3,acc[5][3]);
            xp = pack2(xb.z, xb.z);
            acc[6][0]=ffma2(xp,bv0,acc[6][0]); acc[6][1]=ffma2(xp,bv1,acc[6][1]);
            acc[6][2]=ffma2(xp,bv2,acc[6][2]); acc[6][3]=ffma2(xp,bv3,acc[6][3]);
            xp = pack2(xb.w, xb.w);
            acc[7][0]=ffma2(xp,bv0,acc[7][0]); acc[7][1]=ffma2(xp,bv1,acc[7][1]);
            acc[7][2]=ffma2(xp,bv2,acc[7][2]); acc[7][3]=ffma2(xp,bv3,acc[7][3]);
        }

        // rows in pairs: build+sort both, then 2-way interleaved local extraction.
        // Local output: sorted top-16 of this 256-col half, written in rank order.
#pragma unroll 1
        for (int rp = 0; rp < 4; rp++) {
            ull head[2]; int ptr[2];
#pragma unroll
            for (int rr = 0; rr < 2; rr++) {
                int r = rp*2 + rr;
                int i = i0 + r;
                float sqi = sq[i];
                ull key[8];
#pragma unroll
                for (int t = 0; t < 4; t++) {
                    int p = lane + 32*t;                     // ull index within half
                    float2 dp = unpack2(acc[r][t]);
                    float2 sp = ((const float2*)sq)[halfc*128 + p];
                    float d0 = fmaf(-2.f, dp.x, sqi + sp.x);
                    float d1 = fmaf(-2.f, dp.y, sqi + sp.y);
                    int c0 = halfc*256 + 2*p, c1 = c0 + 1;
                    key[2*t]   = (c0 == i) ? ~0ull : (((ull)fflip(d0) << 32) | (unsigned)c0);
                    key[2*t+1] = (c1 == i) ? ~0ull : (((ull)fflip(d1) << 32) | (unsigned)c1);
                }
                sort8(key);
#pragma unroll
                for (int s = 0; s < 8; s++) wloc[rr*256 + s*32 + lane] = key[s];
                head[rr] = key[0];
                ptr[rr] = 0;
            }
            __syncwarp();

            ull* mrow0 = mergeBuf + (size_t)(pairw*8 + rp*2    ) * 32 + halfc*16;
            ull* mrow1 = mergeBuf + (size_t)(pairw*8 + rp*2 + 1) * 32 + halfc*16;

#pragma unroll 1
            for (int rd = 0; rd < KNN; rd++) {
#pragma unroll
                for (int rr = 0; rr < 2; rr++) {
                    unsigned hi  = (unsigned)(head[rr] >> 32);
                    unsigned mhi = __reduce_min_sync(0xffffffffu, hi);
                    unsigned lo  = (hi == mhi) ? (unsigned)head[rr] : 0xffffffffu;
                    unsigned mlo = __reduce_min_sync(0xffffffffu, lo);
                    if (lane == rd) (rr ? mrow1 : mrow0)[rd] = ((ull)mhi << 32) | mlo;
                    bool win = (hi == mhi) & ((unsigned)head[rr] == mlo);
                    if (win) {
                        ptr[rr]++;
                        head[rr] = (ptr[rr] < 8) ? wloc[rr*256 + ptr[rr]*32 + lane] : ~0ull;
                    }
                }
            }
            __syncwarp();
        }

        __syncthreads();   // all local sorted top-16s visible

        // merge: bitonic-32 clean. Lanes 0-15 load half0 sorted-16 ascending,
        // lanes 16-31 load half1 sorted-16 reversed -> bitonic across warp.
        // 5 shfl-xor compare-exchange stages sort ascending; lanes 0-15 = top-16.
#pragma unroll 1
        for (int rm = 0; rm < 2; rm++) {
            int rloc0 = halfc*4 + rm*2;
            const ull* mr0 = mergeBuf + (size_t)(pairw*8 + rloc0    ) * 32;
            const ull* mr1 = mergeBuf + (size_t)(pairw*8 + rloc0 + 1) * 32;
            int idx = (lane < 16) ? lane : (16 + 31 - lane);
            ull v0 = mr0[idx];
            ull v1 = mr1[idx];
#pragma unroll
            for (int dd = 16; dd >= 1; dd >>= 1) {
                bool up = (lane & dd);
                ull o0 = __shfl_xor_sync(0xffffffffu, v0, dd);
                v0 = up ? (v0 > o0 ? v0 : o0) : (v0 < o0 ? v0 : o0);
                ull o1 = __shfl_xor_sync(0xffffffffu, v1, dd);
                v1 = up ? (v1 > o1 ? v1 : o1) : (v1 < o1 ? v1 : o1);
            }
            if (lane < KNN) {
                kn[((size_t)b*NN + i0 + rloc0    )*KNN + lane] = (int)(unsigned)v0;
                kn[((size_t)b*NN + i0 + rloc0 + 1)*KNN + lane] = (int)(unsigned)v1;
            }
        }

        __syncthreads();   // mergeBuf reusable next pass
    }
}

// ---------------- EdgeConv per-edge: 1 node/warp, 8 nodes/block, 3 blocks/SM (85-reg cap) ----
__global__ __launch_bounds__(256, 3) void k_edge(const float* __restrict__ A,
                                                 const float* __restrict__ U,
                                                 const int* __restrict__ kn,
                                                 const float* __restrict__ W1,
                                                 const float* __restrict__ b1,
                                                 float* __restrict__ hout)
{
    extern __shared__ __align__(16) char esm[];
    float* sW  = (float*)esm;                      // [64*64] = 16KB
    float* sb  = sW + HH*HH;                       // [64]
    float* e0s = sb + HH;                          // [8 nodes][64][20] = 40KB

    int tid = threadIdx.x;
    for (int i = tid; i < HH*HH; i += 256) sW[i] = W1[i];
    if (tid < HH) sb[tid] = b1[tid];
    __syncthreads();

    int w = tid >> 5, l = tid & 31;
    int node = blockIdx.x * 8 + w;
    int base = node & ~(NN - 1);
    float a0 = A[node*HH + l];
    float a1 = A[node*HH + l + 32];
    const int* kp = kn + node*KNN;
    float* e0 = e0s + (size_t)w * (HH*20);

#pragma unroll
    for (int k = 0; k < KNN; k++) {
        const float* up = U + (size_t)(base + kp[k]) * HH;
        e0[l*20 + k]      = elu1(a0 + up[l]);
        e0[(l+32)*20 + k] = elu1(a1 + up[l + 32]);
    }
    __syncwarp();

    ull v0[8], v1[8];
#pragma unroll
    for (int m = 0; m < 8; m++) { v0[m] = 0ull; v1[m] = 0ull; }

#pragma unroll 4
    for (int d = 0; d < HH; d++) {
        float w0 = sW[d*HH + l];
        float w1 = sW[d*HH + l + 32];
        ull w00 = pack2(w0, w0), w11 = pack2(w1, w1);
        const longlong2* ep = (const longlong2*)&e0[d*20];
#pragma unroll
        for (int m = 0; m < 4; m++) {
            longlong2 q = ep[m];
            v0[2*m]   = ffma2((ull)q.x, w00, v0[2*m]);
            v0[2*m+1] = ffma2((ull)q.y, w00, v0[2*m+1]);
            v1[2*m]   = ffma2((ull)q.x, w11, v1[2*m]);
            v1[2*m+1] = ffma2((ull)q.y, w11, v1[2*m+1]);
        }
    }

    float bb0 = sb[l], bb1 = sb[l + 32];
    float o0 = 0.f, o1 = 0.f;
#pragma unroll
    for (int m = 0; m < 8; m++) {
        float2 p = unpack2(v0[m]); o0 += elu1(p.x + bb0) + elu1(p.y + bb0);
        float2 r = unpack2(v1[m]); o1 += elu1(r.x + bb1) + elu1(r.y + bb1);
    }
    hout[node*HH + l]      = o0;
    hout[node*HH + l + 32] = o1;
}

// ---------------- global max-pool + output MLP + log_softmax ----------------
__global__ __launch_bounds__(64) void k_out(const float* __restrict__ h,
                                            const float* __restrict__ Wo0, const float* __restrict__ bo0,
                                            const float* __restrict__ Wo1, const float* __restrict__ bo1,
                                            const float* __restrict__ Wo2, const float* __restrict__ bo2,
                                            float* __restrict__ out)
{
    int b = blockIdx.x, o = threadIdx.x;
    __shared__ float s0[HH], s1[HH], slog[COUT + 1];
    const float* hb = h + (size_t)b * NN * HH;

    float m = -3.0e38f;
    for (int n = 0; n < NN; n++) m = fmaxf(m, hb[n*HH + o]);
    s0[o] = m;
    __syncthreads();

    float a = bo0[o];
    for (int d = 0; d < HH; d++) a += s0[d] * Wo0[d*HH + o];
    s1[o] = elu1(a);
    __syncthreads();

    a = bo1[o];
    for (int d = 0; d < HH; d++) a += s1[d] * Wo1[d*HH + o];
    __syncthreads();
    s0[o] = elu1(a);
    __syncthreads();

    if (o < COUT) {
        float lg = bo2[o];
        for (int d = 0; d < HH; d++) lg += s0[d] * Wo2[d*COUT + o];
        slog[o] = lg;
    }
    __syncthreads();
    if (o == 0) {
        float mx = -3.0e38f;
        for (int c = 0; c < COUT; c++) mx = fmaxf(mx, slog[c]);
        float s = 0.f;
        for (int c = 0; c < COUT; c++) s += expf(slog[c] - mx);
        slog[COUT] = mx + logf(s);
    }
    __syncthreads();
    if (o < COUT) out[b*COUT + o] = slog[o] - slog[COUT];
}

// ---------------- host launcher ----------------
extern "C" void kernel_launch(void* const* d_in, const int* in_sizes, int n_in,
                              void* d_out, int out_size)
{
    const float* x     = (const float*)d_in[0];
    const float* W_in0 = (const float*)d_in[1];
    const float* b_in0 = (const float*)d_in[2];
    const float* W_in1 = (const float*)d_in[3];
    const float* b_in1 = (const float*)d_in[4];
    const float* W_in2 = (const float*)d_in[5];
    const float* b_in2 = (const float*)d_in[6];
    const float* W_e0  = (const float*)d_in[7];
    const float* b_e0  = (const float*)d_in[8];
    const float* W_e1  = (const float*)d_in[9];
    const float* b_e1  = (const float*)d_in[10];
    const float* W_o0  = (const float*)d_in[11];
    const float* b_o0  = (const float*)d_in[12];
    const float* W_o1  = (const float*)d_in[13];
    const float* b_o1  = (const float*)d_in[14];
    const float* W_o2  = (const float*)d_in[15];
    const float* b_o2  = (const float*)d_in[16];
    float* out = (float*)d_out;

    float *h0, *h1, *A, *U;
    int* kn;
    cudaGetSymbolAddress((void**)&h0, g_h0);
    cudaGetSymbolAddress((void**)&h1, g_h1);
    cudaGetSymbolAddress((void**)&A,  g_A);
    cudaGetSymbolAddress((void**)&U,  g_U);
    cudaGetSymbolAddress((void**)&kn, g_knn);

    // knn3: hT + sq + sbp + union(max(weights 32KB, wloc 64KB + merge 16KB)) = 80KB union
    const int knn_smem  = (HH*HTS + NN + HH) * sizeof(float) + (16*2*8*32 + 64*32) * sizeof(ull);
    // k_edge: sW 16KB + sb + e0s[8][64][20] 40KB = 56.25KB
    const int edge_smem = (HH*HH + HH + 8*HH*20) * sizeof(float);
    cudaFuncSetAttribute(k_knn3, cudaFuncAttributeMaxDynamicSharedMemorySize, knn_smem);
    cudaFuncSetAttribute(k_edge, cudaFuncAttributeMaxDynamicSharedMemorySize, edge_smem);

    // fused input MLP: x -> h0
    k_lin_in<<<NODES/256, 256>>>(x, W_in0, b_in0, W_in1, b_in1, W_in2, b_in2, h0);

    // 2 dynamic-kNN EdgeConv layers: h0 -> h1 -> h0
    for (int l = 0; l < 2; l++) {
        const float* hin  = (l == 0) ? h0 : h1;
        float*       hout = (l == 0) ? h1 : h0;
        k_knn3<<<BB, 512, knn_smem>>>(hin, W_e0 + (size_t)l*2*HH*HH, b_e0 + l*HH, kn, A, U);
        k_edge<<<NODES/8, 256, edge_smem>>>(A, U, kn, W_e1 + (size_t)l*HH*HH, b_e1 + l*HH, hout);
    }

    k_out<<<BB, 64>>>(h0, W_o0, b_o0, W_o1, b_o1, W_o2, b_o2, out);
}

// round 15
// speedup vs baseline: 1.6192x; 1.6192x over previous
#include <cuda_runtime.h>
#include <math.h>

#define BB   128
#define NN   512
#define FIN  5
#define HH   64
#define KNN  16
#define COUT 10
#define NODES (BB*NN)
#define HTS  520   // hT row stride in floats

typedef unsigned long long ull;

// ---------------- scratch (device globals) ----------------
__device__ float g_h0[NODES*HH];
__device__ float g_h1[NODES*HH];
__device__ float g_A [NODES*HH];
__device__ float g_U [NODES*HH];
__device__ int   g_knn[NODES*KNN];

// fast branchless ELU
__device__ __forceinline__ float elu1(float x) {
    float e = __expf(x) - 1.f;
    return x > 0.f ? x : e;
}

// ---- packed f32x2 helpers (Blackwell FFMA2 via PTX) ----
__device__ __forceinline__ ull pack2(float x, float y) {
    ull r; asm("mov.b64 %0, {%1,%2};" : "=l"(r) : "f"(x), "f"(y)); return r;
}
__device__ __forceinline__ float2 unpack2(ull v) {
    float2 f; asm("mov.b64 {%0,%1}, %2;" : "=f"(f.x), "=f"(f.y) : "l"(v)); return f;
}
__device__ __forceinline__ ull ffma2(ull a, ull b, ull c) {
    ull d; asm("fma.rn.f32x2 %0, %1, %2, %3;" : "=l"(d) : "l"(a), "l"(b), "l"(c)); return d;
}

__device__ __forceinline__ unsigned fflip(float f) {
    unsigned u = __float_as_uint(f);
    return ((int)u < 0) ? ~u : (u | 0x80000000u);
}

// Batcher odd-even mergesort, n=8, in-register, fully unrolled
__device__ __forceinline__ void sort8(ull key[8]) {
#pragma unroll
    for (int p = 1; p < 8; p <<= 1) {
#pragma unroll
        for (int k = p; k >= 1; k >>= 1) {
#pragma unroll
            for (int j = k % p; j + k < 8; j += 2*k) {
#pragma unroll
                for (int ii = 0; ii < k; ii++) {
                    int a = ii + j, c = ii + j + k;
                    if (c < 8 && (a / (2*p) == c / (2*p))) {
                        ull lo = key[a] < key[c] ? key[a] : key[c];
                        ull hi = key[a] < key[c] ? key[c] : key[a];
                        key[a] = lo; key[c] = hi;
                    }
                }
            }
        }
    }
}

// ---------------- fused 3-layer input MLP: x[5] -> 64 -> 64 -> 64, all ELU ----------------
__global__ __launch_bounds__(256) void k_lin_in(const float* __restrict__ in,
                                                const float* __restrict__ W0, const float* __restrict__ b0,
                                                const float* __restrict__ W1, const float* __restrict__ b1,
                                                const float* __restrict__ W2, const float* __restrict__ b2,
                                                float* __restrict__ out)
{
    __shared__ __align__(16) float sW0[FIN*HH];
    __shared__ __align__(16) float sW1[HH*HH];
    __shared__ __align__(16) float sW2[HH*HH];
    __shared__ float sb0[HH], sb1[HH], sb2[HH];
    int tid = threadIdx.x;
    for (int i = tid; i < FIN*HH; i += 256) sW0[i] = W0[i];
    for (int i = tid; i < HH*HH; i += 256) { sW1[i] = W1[i]; sW2[i] = W2[i]; }
    if (tid < HH) { sb0[tid] = b0[tid]; sb1[tid] = b1[tid]; sb2[tid] = b2[tid]; }
    __syncthreads();

    int node = blockIdx.x * 256 + tid;
    float xv[FIN];
#pragma unroll
    for (int d = 0; d < FIN; d++) xv[d] = in[node*FIN + d];

    float h[HH];
#pragma unroll
    for (int o = 0; o < HH; o++) {
        float a = sb0[o];
#pragma unroll
        for (int d = 0; d < FIN; d++) a += xv[d] * sW0[d*HH + o];
        h[o] = elu1(a);
    }

    float g[HH];
#pragma unroll 2
    for (int op = 0; op < 32; op++) {
        ull acc = 0ull;
#pragma unroll
        for (int d = 0; d < HH; d++)
            acc = ffma2(pack2(h[d], h[d]), ((const ull*)(sW1 + d*HH))[op], acc);
        float2 p = unpack2(acc);
        g[2*op]   = elu1(p.x + sb1[2*op]);
        g[2*op+1] = elu1(p.y + sb1[2*op+1]);
    }

#pragma unroll 2
    for (int op = 0; op < 32; op++) {
        ull acc = 0ull;
#pragma unroll
        for (int d = 0; d < HH; d++)
            acc = ffma2(pack2(g[d], g[d]), ((const ull*)(sW2 + d*HH))[op], acc);
        float2 p = unpack2(acc);
        float2 o2 = make_float2(elu1(p.x + sb2[2*op]), elu1(p.y + sb2[2*op+1]));
        *(float2*)&out[node*HH + 2*op] = o2;
    }
}

// ---------------- fused A/U pre-GEMMs + kNN, column-split warp pairs ----------------
// 512 threads, 16 warps. Warp pair (2w, 2w+1) handles 8 rows; each warp does 256 cols.
// smem: hT 130KB + sq 2KB + sbp 256B + union{ weights 32KB | wloc[16][2][8][32] 64KB + merge 16KB }
__global__ __launch_bounds__(512) void k_knn3(const float* __restrict__ h,
                                              const float* __restrict__ W0,
                                              const float* __restrict__ b0,
                                              int* __restrict__ kn,
                                              float* __restrict__ A,
                                              float* __restrict__ U)
{
    extern __shared__ __align__(16) char smraw[];
    float* hT  = (float*)smraw;                // [64][HTS]
    float* sq  = hT + HH*HTS;                  // [512]
    float* sbp = sq + NN;                      // [64]
    float* uni = sbp + HH;                     // union region (16-B aligned)
    float* sWb = uni;                          // [4096] (phase A)
    float* sWd = uni + HH*HH;                  // [4096] (phase A)
    ull*   wlocBase = (ull*)uni;               // [16 warps][2 rows][8][32] (phase B)
    ull*   mergeBuf = (ull*)uni + 16*2*8*32;   // [64 rows][32]            (phase B)

    int b = blockIdx.x, tid = threadIdx.x;
    int w = tid >> 5, lane = tid & 31;
    const float* hb = h + (size_t)b * NN * HH;

    // stage EdgeConv layer-0 weights (phase A) + bias
    for (int i = tid; i < HH*HH; i += 512) {
        float wa = W0[i];
        float wb = W0[HH*HH + i];
        sWb[i] = wb;
        sWd[i] = wa - wb;
    }
    if (tid < HH) sbp[tid] = b0[tid];

    // load + transpose features, fold in squared norms
    {
        const float4* src = (const float4*)(hb + (size_t)tid * HH);
        float s = 0.f;
#pragma unroll
        for (int q = 0; q < 16; q++) {
            float4 v = src[q];
            int d = q * 4;
            hT[(d+0)*HTS + tid] = v.x;
            hT[(d+1)*HTS + tid] = v.y;
            hT[(d+2)*HTS + tid] = v.z;
            hT[(d+3)*HTS + tid] = v.w;
            s += v.x*v.x + v.y*v.y + v.z*v.z + v.w*v.w;
        }
        sq[tid] = s;
    }
    __syncthreads();

    // ---------- phase A: A/U pre-GEMMs (weights live in union) ----------
    {
        int node = b*NN + tid;
        float hv[HH];
#pragma unroll
        for (int d = 0; d < HH; d++) hv[d] = hT[d*HTS + tid];

#pragma unroll 2
        for (int op = 0; op < 32; op++) {
            ull au = 0ull, ad = 0ull;
#pragma unroll
            for (int d = 0; d < HH; d++) {
                ull hp = pack2(hv[d], hv[d]);
                au = ffma2(hp, ((const ull*)(sWb + d*HH))[op], au);
                ad = ffma2(hp, ((const ull*)(sWd + d*HH))[op], ad);
            }
            float2 pu = unpack2(au);
            *(float2*)&U[(size_t)node*HH + 2*op] = pu;
            float2 pa = unpack2(ad);
            pa.x += sbp[2*op]; pa.y += sbp[2*op+1];
            *(float2*)&A[(size_t)node*HH + 2*op] = pa;
        }
    }
    __syncthreads();   // weight reads done; union becomes wloc/merge

    // ---------- phase B: kNN, 8 passes; warp pair = 8 rows, warp = 256 cols ----------
    int pairw = w >> 1;        // 0..7: row-group within pass
    int halfc = w & 1;         // column half: cols [halfc*256, +256)
    ull* wloc = wlocBase + w * (2*8*32);

#pragma unroll 1
    for (int pp = 0; pp < 8; pp++) {
        int i0 = pp*64 + pairw*8;      // 8 consecutive rows

        ull acc[8][4];
#pragma unroll
        for (int r = 0; r < 8; r++)
#pragma unroll
            for (int t = 0; t < 4; t++) acc[r][t] = 0ull;

#pragma unroll 2
        for (int d = 0; d < HH; d++) {
            const float* rowp = hT + d*HTS;
            float4 xa = *(const float4*)(rowp + i0);        // broadcast rows i0..i0+3
            float4 xb = *(const float4*)(rowp + i0 + 4);    // rows i0+4..i0+7
            const ull* bp = (const ull*)rowp + halfc*128;   // this warp's 256-col half
            ull bv0 = bp[lane], bv1 = bp[lane+32], bv2 = bp[lane+64], bv3 = bp[lane+96];
            ull xp;
            xp = pack2(xa.x, xa.x);
            acc[0][0]=ffma2(xp,bv0,acc[0][0]); acc[0][1]=ffma2(xp,bv1,acc[0][1]);
            acc[0][2]=ffma2(xp,bv2,acc[0][2]); acc[0][3]=ffma2(xp,bv3,acc[0][3]);
            xp = pack2(xa.y, xa.y);
            acc[1][0]=ffma2(xp,bv0,acc[1][0]); acc[1][1]=ffma2(xp,bv1,acc[1][1]);
            acc[1][2]=ffma2(xp,bv2,acc[1][2]); acc[1][3]=ffma2(xp,bv3,acc[1][3]);
            xp = pack2(xa.z, xa.z);
            acc[2][0]=ffma2(xp,bv0,acc[2][0]); acc[2][1]=ffma2(xp,bv1,acc[2][1]);
            acc[2][2]=ffma2(xp,bv2,acc[2][2]); acc[2][3]=ffma2(xp,bv3,acc[2][3]);
            xp = pack2(xa.w, xa.w);
            acc[3][0]=ffma2(xp,bv0,acc[3][0]); acc[3][1]=ffma2(xp,bv1,acc[3][1]);
            acc[3][2]=ffma2(xp,bv2,acc[3][2]); acc[3][3]=ffma2(xp,bv3,acc[3][3]);
            xp = pack2(xb.x, xb.x);
            acc[4][0]=ffma2(xp,bv0,acc[4][0]); acc[4][1]=ffma2(xp,bv1,acc[4][1]);
            acc[4][2]=ffma2(xp,bv2,acc[4][2]); acc[4][3]=ffma2(xp,bv3,acc[4][3]);
            xp = pack2(xb.y, xb.y);
            acc[5][0]=ffma2(xp,bv0,acc[5][0]); acc[5][1]=ffma2(xp,bv1,acc[5][1]);
            acc[5][2]=ffma2(xp,bv2,acc[5][2]); acc[5][3]=ffma2(xp,bv3,acc[5][3]);
            xp = pack2(xb.z, xb.z);
            acc[6][0]=ffma2(xp,bv0,acc[6][0]); acc[6][1]=ffma2(xp,bv1,acc[6][1]);
            acc[6][2]=ffma2(xp,bv2,acc[6][2]); acc[6][3]=ffma2(xp,bv3,acc[6][3]);
            xp = pack2(xb.w, xb.w);
            acc[7][0]=ffma2(xp,bv0,acc[7][0]); acc[7][1]=ffma2(xp,bv1,acc[7][1]);
            acc[7][2]=ffma2(xp,bv2,acc[7][2]); acc[7][3]=ffma2(xp,bv3,acc[7][3]);
        }

        // rows in pairs: build+sort both, then 2-way interleaved local extraction.
        // Local output: sorted top-16 of this 256-col half, written in rank order.
#pragma unroll 1
        for (int rp = 0; rp < 4; rp++) {
            ull head[2]; int ptr[2];
#pragma unroll
            for (int rr = 0; rr < 2; rr++) {
                int r = rp*2 + rr;
                int i = i0 + r;
                float sqi = sq[i];
                ull key[8];
#pragma unroll
                for (int t = 0; t < 4; t++) {
                    int p = lane + 32*t;                     // ull index within half
                    float2 dp = unpack2(acc[r][t]);
                    float2 sp = ((const float2*)sq)[halfc*128 + p];
                    float d0 = fmaf(-2.f, dp.x, sqi + sp.x);
                    float d1 = fmaf(-2.f, dp.y, sqi + sp.y);
                    int c0 = halfc*256 + 2*p, c1 = c0 + 1;
                    key[2*t]   = (c0 == i) ? ~0ull : (((ull)fflip(d0) << 32) | (unsigned)c0);
                    key[2*t+1] = (c1 == i) ? ~0ull : (((ull)fflip(d1) << 32) | (unsigned)c1);
                }
                sort8(key);
#pragma unroll
                for (int s = 0; s < 8; s++) wloc[rr*256 + s*32 + lane] = key[s];
                head[rr] = key[0];
                ptr[rr] = 0;
            }
            __syncwarp();

            ull* mrow0 = mergeBuf + (size_t)(pairw*8 + rp*2    ) * 32 + halfc*16;
            ull* mrow1 = mergeBuf + (size_t)(pairw*8 + rp*2 + 1) * 32 + halfc*16;

#pragma unroll 1
            for (int rd = 0; rd < KNN; rd++) {
#pragma unroll
                for (int rr = 0; rr < 2; rr++) {
                    unsigned hi  = (unsigned)(head[rr] >> 32);
                    unsigned mhi = __reduce_min_sync(0xffffffffu, hi);
                    unsigned lo  = (hi == mhi) ? (unsigned)head[rr] : 0xffffffffu;
                    unsigned mlo = __reduce_min_sync(0xffffffffu, lo);
                    if (lane == rd) (rr ? mrow1 : mrow0)[rd] = ((ull)mhi << 32) | mlo;
                    bool win = (hi == mhi) & ((unsigned)head[rr] == mlo);
                    if (win) {
                        ptr[rr]++;
                        head[rr] = (ptr[rr] < 8) ? wloc[rr*256 + ptr[rr]*32 + lane] : ~0ull;
                    }
                }
            }
            __syncwarp();
        }

        __syncthreads();   // all local sorted top-16s visible

        // merge: bitonic-32 clean. Lanes 0-15 load half0 sorted-16 ascending,
        // lanes 16-31 load half1 sorted-16 reversed -> bitonic across warp.
        // 5 shfl-xor compare-exchange stages sort ascending; lanes 0-15 = top-16.
#pragma unroll 1
        for (int rm = 0; rm < 2; rm++) {
            int rloc0 = halfc*4 + rm*2;
            const ull* mr0 = mergeBuf + (size_t)(pairw*8 + rloc0    ) * 32;
            const ull* mr1 = mergeBuf + (size_t)(pairw*8 + rloc0 + 1) * 32;
            int idx = (lane < 16) ? lane : (16 + 31 - lane);
            ull v0 = mr0[idx];
            ull v1 = mr1[idx];
#pragma unroll
            for (int dd = 16; dd >= 1; dd >>= 1) {
                bool up = (lane & dd);
                ull o0 = __shfl_xor_sync(0xffffffffu, v0, dd);
                v0 = up ? (v0 > o0 ? v0 : o0) : (v0 < o0 ? v0 : o0);
                ull o1 = __shfl_xor_sync(0xffffffffu, v1, dd);
                v1 = up ? (v1 > o1 ? v1 : o1) : (v1 < o1 ? v1 : o1);
            }
            if (lane < KNN) {
                kn[((size_t)b*NN + i0 + rloc0    )*KNN + lane] = (int)(unsigned)v0;
                kn[((size_t)b*NN + i0 + rloc0 + 1)*KNN + lane] = (int)(unsigned)v1;
            }
        }

        __syncthreads();   // mergeBuf reusable next pass
    }
}

// ---------------- EdgeConv per-edge: 2 nodes/warp, 16 nodes/block, f32x2 FMA ----------------
__global__ __launch_bounds__(256) void k_edge(const float* __restrict__ A,
                                              const float* __restrict__ U,
                                              const int* __restrict__ kn,
                                              const float* __restrict__ W1,
                                              const float* __restrict__ b1,
                                              float* __restrict__ hout)
{
    extern __shared__ __align__(16) char esm[];
    float* sW  = (float*)esm;                      // [64*64]
    float* sb  = sW + HH*HH;                       // [64]
    float* e0s = sb + HH;                          // [16 nodes][64][20]

    int tid = threadIdx.x;
    for (int i = tid; i < HH*HH; i += 256) sW[i] = W1[i];
    if (tid < HH) sb[tid] = b1[tid];
    __syncthreads();

    int w = tid >> 5, l = tid & 31;
    int n0 = blockIdx.x * 16 + w*2;
    int n1 = n0 + 1;
    int base = n0 & ~(NN - 1);
    float a00 = A[n0*HH + l],  a01 = A[n0*HH + l + 32];
    float a10 = A[n1*HH + l],  a11 = A[n1*HH + l + 32];
    const int* kp0 = kn + n0*KNN;
    const int* kp1 = kn + n1*KNN;
    float* e0 = e0s + (size_t)(w*2)   * (HH*20);
    float* e1 = e0s + (size_t)(w*2+1) * (HH*20);

#pragma unroll
    for (int k = 0; k < KNN; k++) {
        const float* up0 = U + (size_t)(base + kp0[k]) * HH;
        e0[l*20 + k]      = elu1(a00 + up0[l]);
        e0[(l+32)*20 + k] = elu1(a01 + up0[l + 32]);
        const float* up1 = U + (size_t)(base + kp1[k]) * HH;
        e1[l*20 + k]      = elu1(a10 + up1[l]);
        e1[(l+32)*20 + k] = elu1(a11 + up1[l + 32]);
    }
    __syncwarp();

    ull v0a[8], v0b[8], v1a[8], v1b[8];
#pragma unroll
    for (int m = 0; m < 8; m++) { v0a[m]=0ull; v0b[m]=0ull; v1a[m]=0ull; v1b[m]=0ull; }

#pragma unroll 4
    for (int d = 0; d < HH; d++) {
        float w0 = sW[d*HH + l];
        float w1 = sW[d*HH + l + 32];
        ull w00 = pack2(w0, w0), w11 = pack2(w1, w1);
        const longlong2* ep0 = (const longlong2*)&e0[d*20];
        const longlong2* ep1 = (const longlong2*)&e1[d*20];
#pragma unroll
        for (int m = 0; m < 4; m++) {
            longlong2 q0 = ep0[m];
            v0a[2*m]   = ffma2((ull)q0.x, w00, v0a[2*m]);
            v0a[2*m+1] = ffma2((ull)q0.y, w00, v0a[2*m+1]);
            v0b[2*m]   = ffma2((ull)q0.x, w11, v0b[2*m]);
            v0b[2*m+1] = ffma2((ull)q0.y, w11, v0b[2*m+1]);
            longlong2 q1 = ep1[m];
            v1a[2*m]   = ffma2((ull)q1.x, w00, v1a[2*m]);
            v1a[2*m+1] = ffma2((ull)q1.y, w00, v1a[2*m+1]);
            v1b[2*m]   = ffma2((ull)q1.x, w11, v1b[2*m]);
            v1b[2*m+1] = ffma2((ull)q1.y, w11, v1b[2*m+1]);
        }
    }

    float bb0 = sb[l], bb1 = sb[l + 32];
    float o0a = 0.f, o0b = 0.f, o1a = 0.f, o1b = 0.f;
#pragma unroll
    for (int m = 0; m < 8; m++) {
        float2 p;
        p = unpack2(v0a[m]); o0a += elu1(p.x + bb0) + elu1(p.y + bb0);
        p = unpack2(v0b[m]); o0b += elu1(p.x + bb1) + elu1(p.y + bb1);
        p = unpack2(v1a[m]); o1a += elu1(p.x + bb0) + elu1(p.y + bb0);
        p = unpack2(v1b[m]); o1b += elu1(p.x + bb1) + elu1(p.y + bb1);
    }
    hout[n0*HH + l]      = o0a;
    hout[n0*HH + l + 32] = o0b;
    hout[n1*HH + l]      = o1a;
    hout[n1*HH + l + 32] = o1b;
}

// ---------------- global max-pool + output MLP + log_softmax ----------------
__global__ __launch_bounds__(64) void k_out(const float* __restrict__ h,
                                            const float* __restrict__ Wo0, const float* __restrict__ bo0,
                                            const float* __restrict__ Wo1, const float* __restrict__ bo1,
                                            const float* __restrict__ Wo2, const float* __restrict__ bo2,
                                            float* __restrict__ out)
{
    int b = blockIdx.x, o = threadIdx.x;
    __shared__ float s0[HH], s1[HH], slog[COUT + 1];
    const float* hb = h + (size_t)b * NN * HH;

    float m = -3.0e38f;
    for (int n = 0; n < NN; n++) m = fmaxf(m, hb[n*HH + o]);
    s0[o] = m;
    __syncthreads();

    float a = bo0[o];
    for (int d = 0; d < HH; d++) a += s0[d] * Wo0[d*HH + o];
    s1[o] = elu1(a);
    __syncthreads();

    a = bo1[o];
    for (int d = 0; d < HH; d++) a += s1[d] * Wo1[d*HH + o];
    __syncthreads();
    s0[o] = elu1(a);
    __syncthreads();

    if (o < COUT) {
        float lg = bo2[o];
        for (int d = 0; d < HH; d++) lg += s0[d] * Wo2[d*COUT + o];
        slog[o] = lg;
    }
    __syncthreads();
    if (o == 0) {
        float mx = -3.0e38f;
        for (int c = 0; c < COUT; c++) mx = fmaxf(mx, slog[c]);
        float s = 0.f;
        for (int c = 0; c < COUT; c++) s += expf(slog[c] - mx);
        slog[COUT] = mx + logf(s);
    }
    __syncthreads();
    if (o < COUT) out[b*COUT + o] = slog[o] - slog[COUT];
}

// ---------------- host launcher ----------------
extern "C" void kernel_launch(void* const* d_in, const int* in_sizes, int n_in,
                              void* d_out, int out_size)
{
    const float* x     = (const float*)d_in[0];
    const float* W_in0 = (const float*)d_in[1];
    const float* b_in0 = (const float*)d_in[2];
    const float* W_in1 = (const float*)d_in[3];
    const float* b_in1 = (const float*)d_in[4];
    const float* W_in2 = (const float*)d_in[5];
    const float* b_in2 = (const float*)d_in[6];
    const float* W_e0  = (const float*)d_in[7];
    const float* b_e0  = (const float*)d_in[8];
    const float* W_e1  = (const float*)d_in[9];
    const float* b_e1  = (const float*)d_in[10];
    const float* W_o0  = (const float*)d_in[11];
    const float* b_o0  = (const float*)d_in[12];
    const float* W_o1  = (const float*)d_in[13];
    const float* b_o1  = (const float*)d_in[14];
    const float* W_o2  = (const float*)d_in[15];
    const float* b_o2  = (const float*)d_in[16];
    float* out = (float*)d_out;

    float *h0, *h1, *A, *U;
    int* kn;
    cudaGetSymbolAddress((void**)&h0, g_h0);
    cudaGetSymbolAddress((void**)&h1, g_h1);
    cudaGetSymbolAddress((void**)&A,  g_A);
    cudaGetSymbolAddress((void**)&U,  g_U);
    cudaGetSymbolAddress((void**)&kn, g_knn);

    // knn3: hT + sq + sbp + union(max(weights 32KB, wloc 64KB + merge 16KB)) = 80KB union
    const int knn_smem  = (HH*HTS + NN + HH) * sizeof(float) + (16*2*8*32 + 64*32) * sizeof(ull);
    // k_edge: sW 16KB + sb + e0s[16][64][20] 80KB = ~96.5KB -> 2 blocks/SM
    const int edge_smem = (HH*HH + HH + 16*HH*20) * sizeof(float);
    cudaFuncSetAttribute(k_knn3, cudaFuncAttributeMaxDynamicSharedMemorySize, knn_smem);
    cudaFuncSetAttribute(k_edge, cudaFuncAttributeMaxDynamicSharedMemorySize, edge_smem);

    // fused input MLP: x -> h0
    k_lin_in<<<NODES/256, 256>>>(x, W_in0, b_in0, W_in1, b_in1, W_in2, b_in2, h0);

    // 2 dynamic-kNN EdgeConv layers: h0 -> h1 -> h0
    for (int l = 0; l < 2; l++) {
        const float* hin  = (l == 0) ? h0 : h1;
        float*       hout = (l == 0) ? h1 : h0;
        k_knn3<<<BB, 512, knn_smem>>>(hin, W_e0 + (size_t)l*2*HH*HH, b_e0 + l*HH, kn, A, U);
        k_edge<<<NODES/16, 256, edge_smem>>>(A, U, kn, W_e1 + (size_t)l*HH*HH, b_e1 + l*HH, hout);
    }

    k_out<<<BB, 64>>>(h0, W_o0, b_o0, W_o1, b_o1, W_o2, b_o2, out);
}

// round 16
// speedup vs baseline: 1.6307x; 1.0071x over previous
#include <cuda_runtime.h>
#include <math.h>

#define BB   128
#define NN   512
#define FIN  5
#define HH   64
#define KNN  16
#define COUT 10
#define NODES (BB*NN)
#define HTS  520   // hT row stride in floats

typedef unsigned long long ull;

// ---------------- scratch (device globals) ----------------
__device__ float g_h0[NODES*HH];
__device__ float g_h1[NODES*HH];
__device__ float g_A [NODES*HH];
__device__ float g_U [NODES*HH];
__device__ int   g_knn[NODES*KNN];

// fast branchless ELU
__device__ __forceinline__ float elu1(float x) {
    float e = __expf(x) - 1.f;
    return x > 0.f ? x : e;
}

// ---- packed f32x2 helpers (Blackwell FFMA2 via PTX) ----
__device__ __forceinline__ ull pack2(float x, float y) {
    ull r; asm("mov.b64 %0, {%1,%2};" : "=l"(r) : "f"(x), "f"(y)); return r;
}
__device__ __forceinline__ float2 unpack2(ull v) {
    float2 f; asm("mov.b64 {%0,%1}, %2;" : "=f"(f.x), "=f"(f.y) : "l"(v)); return f;
}
__device__ __forceinline__ ull ffma2(ull a, ull b, ull c) {
    ull d; asm("fma.rn.f32x2 %0, %1, %2, %3;" : "=l"(d) : "l"(a), "l"(b), "l"(c)); return d;
}

__device__ __forceinline__ unsigned fflip(float f) {
    unsigned u = __float_as_uint(f);
    return ((int)u < 0) ? ~u : (u | 0x80000000u);
}

// Batcher odd-even mergesort, n=8, in-register, fully unrolled
__device__ __forceinline__ void sort8(ull key[8]) {
#pragma unroll
    for (int p = 1; p < 8; p <<= 1) {
#pragma unroll
        for (int k = p; k >= 1; k >>= 1) {
#pragma unroll
            for (int j = k % p; j + k < 8; j += 2*k) {
#pragma unroll
                for (int ii = 0; ii < k; ii++) {
                    int a = ii + j, c = ii + j + k;
                    if (c < 8 && (a / (2*p) == c / (2*p))) {
                        ull lo = key[a] < key[c] ? key[a] : key[c];
                        ull hi = key[a] < key[c] ? key[c] : key[a];
                        key[a] = lo; key[c] = hi;
                    }
                }
            }
        }
    }
}

// ---------------- fused 3-layer input MLP: x[5] -> 64 -> 64 -> 64, all ELU ----------------
__global__ __launch_bounds__(256) void k_lin_in(const float* __restrict__ in,
                                                const float* __restrict__ W0, const float* __restrict__ b0,
                                                const float* __restrict__ W1, const float* __restrict__ b1,
                                                const float* __restrict__ W2, const float* __restrict__ b2,
                                                float* __restrict__ out)
{
    __shared__ __align__(16) float sW0[FIN*HH];
    __shared__ __align__(16) float sW1[HH*HH];
    __shared__ __align__(16) float sW2[HH*HH];
    __shared__ float sb0[HH], sb1[HH], sb2[HH];
    int tid = threadIdx.x;
    for (int i = tid; i < FIN*HH; i += 256) sW0[i] = W0[i];
    for (int i = tid; i < HH*HH; i += 256) { sW1[i] = W1[i]; sW2[i] = W2[i]; }
    if (tid < HH) { sb0[tid] = b0[tid]; sb1[tid] = b1[tid]; sb2[tid] = b2[tid]; }
    __syncthreads();

    int node = blockIdx.x * 256 + tid;
    float xv[FIN];
#pragma unroll
    for (int d = 0; d < FIN; d++) xv[d] = in[node*FIN + d];

    float h[HH];
#pragma unroll
    for (int o = 0; o < HH; o++) {
        float a = sb0[o];
#pragma unroll
        for (int d = 0; d < FIN; d++) a += xv[d] * sW0[d*HH + o];
        h[o] = elu1(a);
    }

    float g[HH];
#pragma unroll 2
    for (int op = 0; op < 32; op++) {
        ull acc = 0ull;
#pragma unroll
        for (int d = 0; d < HH; d++)
            acc = ffma2(pack2(h[d], h[d]), ((const ull*)(sW1 + d*HH))[op], acc);
        float2 p = unpack2(acc);
        g[2*op]   = elu1(p.x + sb1[2*op]);
        g[2*op+1] = elu1(p.y + sb1[2*op+1]);
    }

#pragma unroll 2
    for (int op = 0; op < 32; op++) {
        ull acc = 0ull;
#pragma unroll
        for (int d = 0; d < HH; d++)
            acc = ffma2(pack2(g[d], g[d]), ((const ull*)(sW2 + d*HH))[op], acc);
        float2 p = unpack2(acc);
        float2 o2 = make_float2(elu1(p.x + sb2[2*op]), elu1(p.y + sb2[2*op+1]));
        *(float2*)&out[node*HH + 2*op] = o2;
    }
}

// ---------------- fused A/U pre-GEMMs + kNN, column-split warp pairs ----------------
// 512 threads, 16 warps. Warp pair (2w, 2w+1) handles 8 rows; each warp does 256 cols.
// smem: hT 130KB + sq 2KB + sbp 256B + union{ weights 32KB | wloc[16][2][8][32] 64KB + merge 16KB }
__global__ __launch_bounds__(512) void k_knn3(const float* __restrict__ h,
                                              const float* __restrict__ W0,
                                              const float* __restrict__ b0,
                                              int* __restrict__ kn,
                                              float* __restrict__ A,
                                              float* __restrict__ U)
{
    extern __shared__ __align__(16) char smraw[];
    float* hT  = (float*)smraw;                // [64][HTS]
    float* sq  = hT + HH*HTS;                  // [512]
    float* sbp = sq + NN;                      // [64]
    float* uni = sbp + HH;                     // union region (16-B aligned)
    float* sWb = uni;                          // [4096] (phase A)
    float* sWd = uni + HH*HH;                  // [4096] (phase A)
    ull*   wlocBase = (ull*)uni;               // [16 warps][2 rows][8][32] (phase B)
    ull*   mergeBuf = (ull*)uni + 16*2*8*32;   // [64 rows][32]            (phase B)

    int b = blockIdx.x, tid = threadIdx.x;
    int w = tid >> 5, lane = tid & 31;
    const float* hb = h + (size_t)b * NN * HH;

    // stage EdgeConv layer-0 weights (phase A) + bias
    for (int i = tid; i < HH*HH; i += 512) {
        float wa = W0[i];
        float wb = W0[HH*HH + i];
        sWb[i] = wb;
        sWd[i] = wa - wb;
    }
    if (tid < HH) sbp[tid] = b0[tid];

    // load + transpose features, fold in squared norms
    {
        const float4* src = (const float4*)(hb + (size_t)tid * HH);
        float s = 0.f;
#pragma unroll
        for (int q = 0; q < 16; q++) {
            float4 v = src[q];
            int d = q * 4;
            hT[(d+0)*HTS + tid] = v.x;
            hT[(d+1)*HTS + tid] = v.y;
            hT[(d+2)*HTS + tid] = v.z;
            hT[(d+3)*HTS + tid] = v.w;
            s += v.x*v.x + v.y*v.y + v.z*v.z + v.w*v.w;
        }
        sq[tid] = s;
    }
    __syncthreads();

    // ---------- phase A: A/U pre-GEMMs (weights live in union) ----------
    {
        int node = b*NN + tid;
        float hv[HH];
#pragma unroll
        for (int d = 0; d < HH; d++) hv[d] = hT[d*HTS + tid];

#pragma unroll 2
        for (int op = 0; op < 32; op++) {
            ull au = 0ull, ad = 0ull;
#pragma unroll
            for (int d = 0; d < HH; d++) {
                ull hp = pack2(hv[d], hv[d]);
                au = ffma2(hp, ((const ull*)(sWb + d*HH))[op], au);
                ad = ffma2(hp, ((const ull*)(sWd + d*HH))[op], ad);
            }
            float2 pu = unpack2(au);
            *(float2*)&U[(size_t)node*HH + 2*op] = pu;
            float2 pa = unpack2(ad);
            pa.x += sbp[2*op]; pa.y += sbp[2*op+1];
            *(float2*)&A[(size_t)node*HH + 2*op] = pa;
        }
    }
    __syncthreads();   // weight reads done; union becomes wloc/merge

    // ---------- phase B: kNN, 8 passes; warp pair = 8 rows, warp = 256 cols ----------
    int pairw = w >> 1;        // 0..7: row-group within pass
    int halfc = w & 1;         // column half: cols [halfc*256, +256)
    ull* wloc = wlocBase + w * (2*8*32);

#pragma unroll 1
    for (int pp = 0; pp < 8; pp++) {
        int i0 = pp*64 + pairw*8;      // 8 consecutive rows

        ull acc[8][4];
#pragma unroll
        for (int r = 0; r < 8; r++)
#pragma unroll
            for (int t = 0; t < 4; t++) acc[r][t] = 0ull;

#pragma unroll 2
        for (int d = 0; d < HH; d++) {
            const float* rowp = hT + d*HTS;
            float4 xa = *(const float4*)(rowp + i0);        // broadcast rows i0..i0+3
            float4 xb = *(const float4*)(rowp + i0 + 4);    // rows i0+4..i0+7
            const ull* bp = (const ull*)rowp + halfc*128;   // this warp's 256-col half
            ull bv0 = bp[lane], bv1 = bp[lane+32], bv2 = bp[lane+64], bv3 = bp[lane+96];
            ull xp;
            xp = pack2(xa.x, xa.x);
            acc[0][0]=ffma2(xp,bv0,acc[0][0]); acc[0][1]=ffma2(xp,bv1,acc[0][1]);
            acc[0][2]=ffma2(xp,bv2,acc[0][2]); acc[0][3]=ffma2(xp,bv3,acc[0][3]);
            xp = pack2(xa.y, xa.y);
            acc[1][0]=ffma2(xp,bv0,acc[1][0]); acc[1][1]=ffma2(xp,bv1,acc[1][1]);
            acc[1][2]=ffma2(xp,bv2,acc[1][2]); acc[1][3]=ffma2(xp,bv3,acc[1][3]);
            xp = pack2(xa.z, xa.z);
            acc[2][0]=ffma2(xp,bv0,acc[2][0]); acc[2][1]=ffma2(xp,bv1,acc[2][1]);
            acc[2][2]=ffma2(xp,bv2,acc[2][2]); acc[2][3]=ffma2(xp,bv3,acc[2][3]);
            xp = pack2(xa.w, xa.w);
            acc[3][0]=ffma2(xp,bv0,acc[3][0]); acc[3][1]=ffma2(xp,bv1,acc[3][1]);
            acc[3][2]=ffma2(xp,bv2,acc[3][2]); acc[3][3]=ffma2(xp,bv3,acc[3][3]);
            xp = pack2(xb.x, xb.x);
            acc[4][0]=ffma2(xp,bv0,acc[4][0]); acc[4][1]=ffma2(xp,bv1,acc[4][1]);
            acc[4][2]=ffma2(xp,bv2,acc[4][2]); acc[4][3]=ffma2(xp,bv3,acc[4][3]);
            xp = pack2(xb.y, xb.y);
            acc[5][0]=ffma2(xp,bv0,acc[5][0]); acc[5][1]=ffma2(xp,bv1,acc[5][1]);
            acc[5][2]=ffma2(xp,bv2,acc[5][2]); acc[5][3]=ffma2(xp,bv3,acc[5][3]);
            xp = pack2(xb.z, xb.z);
            acc[6][0]=ffma2(xp,bv0,acc[6][0]); acc[6][1]=ffma2(xp,bv1,acc[6][1]);
            acc[6][2]=ffma2(xp,bv2,acc[6][2]); acc[6][3]=ffma2(xp,bv3,acc[6][3]);
            xp = pack2(xb.w, xb.w);
            acc[7][0]=ffma2(xp,bv0,acc[7][0]); acc[7][1]=ffma2(xp,bv1,acc[7][1]);
            acc[7][2]=ffma2(xp,bv2,acc[7][2]); acc[7][3]=ffma2(xp,bv3,acc[7][3]);
        }

        // rows in pairs: build+sort both, then 2-way interleaved local extraction.
        // Local output: sorted top-16 of this 256-col half, written in rank order.
#pragma unroll 1
        for (int rp = 0; rp < 4; rp++) {
            ull head[2]; int ptr[2];
#pragma unroll
            for (int rr = 0; rr < 2; rr++) {
                int r = rp*2 + rr;
                int i = i0 + r;
                float sqi = sq[i];
                ull key[8];
#pragma unroll
                for (int t = 0; t < 4; t++) {
                    int p = lane + 32*t;                     // ull index within half
                    float2 dp = unpack2(acc[r][t]);
                    float2 sp = ((const float2*)sq)[halfc*128 + p];
                    float d0 = fmaf(-2.f, dp.x, sqi + sp.x);
                    float d1 = fmaf(-2.f, dp.y, sqi + sp.y);
                    int c0 = halfc*256 + 2*p, c1 = c0 + 1;
                    key[2*t]   = (c0 == i) ? ~0ull : (((ull)fflip(d0) << 32) | (unsigned)c0);
                    key[2*t+1] = (c1 == i) ? ~0ull : (((ull)fflip(d1) << 32) | (unsigned)c1);
                }
                sort8(key);
#pragma unroll
                for (int s = 0; s < 8; s++) wloc[rr*256 + s*32 + lane] = key[s];
                head[rr] = key[0];
                ptr[rr] = 0;
            }
            __syncwarp();

            ull* mrow0 = mergeBuf + (size_t)(pairw*8 + rp*2    ) * 32 + halfc*16;
            ull* mrow1 = mergeBuf + (size_t)(pairw*8 + rp*2 + 1) * 32 + halfc*16;

#pragma unroll 1
            for (int rd = 0; rd < KNN; rd++) {
#pragma unroll
                for (int rr = 0; rr < 2; rr++) {
                    unsigned hi  = (unsigned)(head[rr] >> 32);
                    unsigned mhi = __reduce_min_sync(0xffffffffu, hi);
                    unsigned lo  = (hi == mhi) ? (unsigned)head[rr] : 0xffffffffu;
                    unsigned mlo = __reduce_min_sync(0xffffffffu, lo);
                    if (lane == rd) (rr ? mrow1 : mrow0)[rd] = ((ull)mhi << 32) | mlo;
                    bool win = (hi == mhi) & ((unsigned)head[rr] == mlo);
                    if (win) {
                        ptr[rr]++;
                        head[rr] = (ptr[rr] < 8) ? wloc[rr*256 + ptr[rr]*32 + lane] : ~0ull;
                    }
                }
            }
            __syncwarp();
        }

        __syncthreads();   // all local sorted top-16s visible

        // merge: bitonic-32 clean. Lanes 0-15 load half0 sorted-16 ascending,
        // lanes 16-31 load half1 sorted-16 reversed -> bitonic across warp.
        // 5 shfl-xor compare-exchange stages sort ascending; lanes 0-15 = top-16.
#pragma unroll 1
        for (int rm = 0; rm < 2; rm++) {
            int rloc0 = halfc*4 + rm*2;
            const ull* mr0 = mergeBuf + (size_t)(pairw*8 + rloc0    ) * 32;
            const ull* mr1 = mergeBuf + (size_t)(pairw*8 + rloc0 + 1) * 32;
            int idx = (lane < 16) ? lane : (16 + 31 - lane);
            ull v0 = mr0[idx];
            ull v1 = mr1[idx];
#pragma unroll
            for (int dd = 16; dd >= 1; dd >>= 1) {
                bool up = (lane & dd);
                ull o0 = __shfl_xor_sync(0xffffffffu, v0, dd);
                v0 = up ? (v0 > o0 ? v0 : o0) : (v0 < o0 ? v0 : o0);
                ull o1 = __shfl_xor_sync(0xffffffffu, v1, dd);
                v1 = up ? (v1 > o1 ? v1 : o1) : (v1 < o1 ? v1 : o1);
            }
            if (lane < KNN) {
                kn[((size_t)b*NN + i0 + rloc0    )*KNN + lane] = (int)(unsigned)v0;
                kn[((size_t)b*NN + i0 + rloc0 + 1)*KNN + lane] = (int)(unsigned)v1;
            }
        }

        __syncthreads();   // mergeBuf reusable next pass
    }
}

// ---------------- EdgeConv per-edge: 1 node/warp, 8 nodes/block, 3 blocks/SM (85-reg cap) ----
__global__ __launch_bounds__(256, 3) void k_edge(const float* __restrict__ A,
                                                 const float* __restrict__ U,
                                                 const int* __restrict__ kn,
                                                 const float* __restrict__ W1,
                                                 const float* __restrict__ b1,
                                                 float* __restrict__ hout)
{
    extern __shared__ __align__(16) char esm[];
    float* sW  = (float*)esm;                      // [64*64] = 16KB
    float* sb  = sW + HH*HH;                       // [64]
    float* e0s = sb + HH;                          // [8 nodes][64][20] = 40KB

    int tid = threadIdx.x;
    for (int i = tid; i < HH*HH; i += 256) sW[i] = W1[i];
    if (tid < HH) sb[tid] = b1[tid];
    __syncthreads();

    int w = tid >> 5, l = tid & 31;
    int node = blockIdx.x * 8 + w;
    int base = node & ~(NN - 1);
    float a0 = A[node*HH + l];
    float a1 = A[node*HH + l + 32];
    const int* kp = kn + node*KNN;
    float* e0 = e0s + (size_t)w * (HH*20);

#pragma unroll
    for (int k = 0; k < KNN; k++) {
        const float* up = U + (size_t)(base + kp[k]) * HH;
        e0[l*20 + k]      = elu1(a0 + up[l]);
        e0[(l+32)*20 + k] = elu1(a1 + up[l + 32]);
    }
    __syncwarp();

    ull v0[8], v1[8];
#pragma unroll
    for (int m = 0; m < 8; m++) { v0[m] = 0ull; v1[m] = 0ull; }

#pragma unroll 4
    for (int d = 0; d < HH; d++) {
        float w0 = sW[d*HH + l];
        float w1 = sW[d*HH + l + 32];
        ull w00 = pack2(w0, w0), w11 = pack2(w1, w1);
        const longlong2* ep = (const longlong2*)&e0[d*20];
#pragma unroll
        for (int m = 0; m < 4; m++) {
            longlong2 q = ep[m];
            v0[2*m]   = ffma2((ull)q.x, w00, v0[2*m]);
            v0[2*m+1] = ffma2((ull)q.y, w00, v0[2*m+1]);
            v1[2*m]   = ffma2((ull)q.x, w11, v1[2*m]);
            v1[2*m+1] = ffma2((ull)q.y, w11, v1[2*m+1]);
        }
    }

    float bb0 = sb[l], bb1 = sb[l + 32];
    float o0 = 0.f, o1 = 0.f;
#pragma unroll
    for (int m = 0; m < 8; m++) {
        float2 p = unpack2(v0[m]); o0 += elu1(p.x + bb0) + elu1(p.y + bb0);
        float2 r = unpack2(v1[m]); o1 += elu1(r.x + bb1) + elu1(r.y + bb1);
    }
    hout[node*HH + l]      = o0;
    hout[node*HH + l + 32] = o1;
}

// ---------------- global max-pool + output MLP + log_softmax ----------------
__global__ __launch_bounds__(64) void k_out(const float* __restrict__ h,
                                            const float* __restrict__ Wo0, const float* __restrict__ bo0,
                                            const float* __restrict__ Wo1, const float* __restrict__ bo1,
                                            const float* __restrict__ Wo2, const float* __restrict__ bo2,
                                            float* __restrict__ out)
{
    int b = blockIdx.x, o = threadIdx.x;
    __shared__ float s0[HH], s1[HH], slog[COUT + 1];
    const float* hb = h + (size_t)b * NN * HH;

    float m = -3.0e38f;
    for (int n = 0; n < NN; n++) m = fmaxf(m, hb[n*HH + o]);
    s0[o] = m;
    __syncthreads();

    float a = bo0[o];
    for (int d = 0; d < HH; d++) a += s0[d] * Wo0[d*HH + o];
    s1[o] = elu1(a);
    __syncthreads();

    a = bo1[o];
    for (int d = 0; d < HH; d++) a += s1[d] * Wo1[d*HH + o];
    __syncthreads();
    s0[o] = elu1(a);
    __syncthreads();

    if (o < COUT) {
        float lg = bo2[o];
        for (int d = 0; d < HH; d++) lg += s0[d] * Wo2[d*COUT + o];
        slog[o] = lg;
    }
    __syncthreads();
    if (o == 0) {
        float mx = -3.0e38f;
        for (int c = 0; c < COUT; c++) mx = fmaxf(mx, slog[c]);
        float s = 0.f;
        for (int c = 0; c < COUT; c++) s += expf(slog[c] - mx);
        slog[COUT] = mx + logf(s);
    }
    __syncthreads();
    if (o < COUT) out[b*COUT + o] = slog[o] - slog[COUT];
}

// ---------------- host launcher ----------------
extern "C" void kernel_launch(void* const* d_in, const int* in_sizes, int n_in,
                              void* d_out, int out_size)
{
    const float* x     = (const float*)d_in[0];
    const float* W_in0 = (const float*)d_in[1];
    const float* b_in0 = (const float*)d_in[2];
    const float* W_in1 = (const float*)d_in[3];
    const float* b_in1 = (const float*)d_in[4];
    const float* W_in2 = (const float*)d_in[5];
    const float* b_in2 = (const float*)d_in[6];
    const float* W_e0  = (const float*)d_in[7];
    const float* b_e0  = (const float*)d_in[8];
    const float* W_e1  = (const float*)d_in[9];
    const float* b_e1  = (const float*)d_in[10];
    const float* W_o0  = (const float*)d_in[11];
    const float* b_o0  = (const float*)d_in[12];
    const float* W_o1  = (const float*)d_in[13];
    const float* b_o1  = (const float*)d_in[14];
    const float* W_o2  = (const float*)d_in[15];
    const float* b_o2  = (const float*)d_in[16];
    float* out = (float*)d_out;

    float *h0, *h1, *A, *U;
    int* kn;
    cudaGetSymbolAddress((void**)&h0, g_h0);
    cudaGetSymbolAddress((void**)&h1, g_h1);
    cudaGetSymbolAddress((void**)&A,  g_A);
    cudaGetSymbolAddress((void**)&U,  g_U);
    cudaGetSymbolAddress((void**)&kn, g_knn);

    // knn3: hT + sq + sbp + union(max(weights 32KB, wloc 64KB + merge 16KB)) = 80KB union
    const int knn_smem  = (HH*HTS + NN + HH) * sizeof(float) + (16*2*8*32 + 64*32) * sizeof(ull);
    // k_edge: sW 16KB + sb + e0s[8][64][20] 40KB = 56.25KB -> 3 blocks/SM (reg-limited)
    const int edge_smem = (HH*HH + HH + 8*HH*20) * sizeof(float);
    cudaFuncSetAttribute(k_knn3, cudaFuncAttributeMaxDynamicSharedMemorySize, knn_smem);
    cudaFuncSetAttribute(k_edge, cudaFuncAttributeMaxDynamicSharedMemorySize, edge_smem);

    // fused input MLP: x -> h0
    k_lin_in<<<NODES/256, 256>>>(x, W_in0, b_in0, W_in1, b_in1, W_in2, b_in2, h0);

    // 2 dynamic-kNN EdgeConv layers: h0 -> h1 -> h0
    for (int l = 0; l < 2; l++) {
        const float* hin  = (l == 0) ? h0 : h1;
        float*       hout = (l == 0) ? h1 : h0;
        k_knn3<<<BB, 512, knn_smem>>>(hin, W_e0 + (size_t)l*2*HH*HH, b_e0 + l*HH, kn, A, U);
        k_edge<<<NODES/8, 256, edge_smem>>>(A, U, kn, W_e1 + (size_t)l*HH*HH, b_e1 + l*HH, hout);
    }

    k_out<<<BB, 64>>>(h0, W_o0, b_o0, W_o1, b_o1, W_o2, b_o2, out);
}